// round 8
// baseline (speedup 1.0000x reference)
#include <cuda_runtime.h>
#include <cuda_fp16.h>
#include <cstdint>

// LSTM cell: single-pass fp16 GEMM (fp32 acc) via mma.sync, warp tile 64x64,
// BN=256, register-pipelined fragments + fused gate epilogue.
// z = [X|H] @ [W;R] (+bias); out = [h | h | c].
// B columns permuted: col' = 4*u + gate.

#define MB   8192
#define KK   1024
#define NTOT 2048
#define UU   512
#define BM   128
#define BN   256
#define BK   32
#define KT   (KK / BK)              // 32 k-iterations
#define ROWB 80                     // smem row stride bytes
#define ATILE (128 * ROWB)          // 10240
#define BTILE (256 * ROWB)          // 20480
#define STAGEB (ATILE + BTILE)      // 30720
#define NSTG 4
#define SMEM_DYN 133120             // max(4*STAGEB=122880, 128*260*4=133120)

#define CONVA_BLOCKS (MB * KK / 8 / 256)   // 4096
#define CONVB_BX     (NTOT / 32)           // 64
#define CONVB_BLOCKS (CONVB_BX * (KK / 64))

// -------- device scratch --------
__device__ __half g_A[(size_t)MB * KK];
__device__ __half g_B[(size_t)NTOT * KK];

// -------- helpers --------
__device__ __forceinline__ uint32_t s2u(const void* p) {
    uint32_t a;
    asm("{ .reg .u64 t; cvta.to.shared.u64 t, %1; cvt.u32.u64 %0, t; }"
        : "=r"(a) : "l"(p));
    return a;
}
__device__ __forceinline__ void cp16(uint32_t dst, const void* src) {
    asm volatile("cp.async.cg.shared.global [%0], [%1], 16;"
                 :: "r"(dst), "l"((unsigned long long)__cvta_generic_to_global(src))
                 : "memory");
}
#define CP_COMMIT() asm volatile("cp.async.commit_group;" ::: "memory")
#define CP_WAIT2()  asm volatile("cp.async.wait_group 2;" ::: "memory")

__device__ __forceinline__ void ldsm4(uint32_t* r, uint32_t addr) {
    asm volatile("ldmatrix.sync.aligned.m8n8.x4.shared.b16 {%0,%1,%2,%3}, [%4];"
                 : "=r"(r[0]), "=r"(r[1]), "=r"(r[2]), "=r"(r[3]) : "r"(addr));
}
__device__ __forceinline__ void mma16816(float* d, const uint32_t* a,
                                         const uint32_t* b) {
    asm volatile(
        "mma.sync.aligned.m16n8k16.row.col.f32.f16.f16.f32 "
        "{%0,%1,%2,%3}, {%4,%5,%6,%7}, {%8,%9}, {%0,%1,%2,%3};"
        : "+f"(d[0]), "+f"(d[1]), "+f"(d[2]), "+f"(d[3])
        : "r"(a[0]), "r"(a[1]), "r"(a[2]), "r"(a[3]), "r"(b[0]), "r"(b[1]));
}
__device__ __forceinline__ float ex2f(float x) {
    float y; asm("ex2.approx.f32 %0, %1;" : "=f"(y) : "f"(x)); return y;
}
__device__ __forceinline__ float rcpf(float x) {
    float y; asm("rcp.approx.f32 %0, %1;" : "=f"(y) : "f"(x)); return y;
}
__device__ __forceinline__ float sigf(float x) {
    return rcpf(1.0f + ex2f(-1.4426950408889634f * x));
}
__device__ __forceinline__ float tanhf_fast(float x) {
    return 1.0f - 2.0f * rcpf(1.0f + ex2f(2.8853900817779268f * x));
}

// -------- merged conversion kernel (R7-proven) --------
__global__ __launch_bounds__(256)
void conv_all(const float* __restrict__ X, const float* __restrict__ H,
              const float* __restrict__ W, const float* __restrict__ R)
{
    __shared__ __half s[64][34];
    if (blockIdx.x < CONVA_BLOCKS) {
        int idx = blockIdx.x * 256 + threadIdx.x;
        int row = idx >> 7;
        int c8  = (idx & 127) * 8;
        const float4* src = (c8 < 512)
            ? (const float4*)(X + (size_t)row * 512 + c8)
            : (const float4*)(H + (size_t)row * 512 + (c8 - 512));
        float4 v0 = src[0], v1 = src[1];
        __half h[8];
        h[0] = __float2half(v0.x); h[1] = __float2half(v0.y);
        h[2] = __float2half(v0.z); h[3] = __float2half(v0.w);
        h[4] = __float2half(v1.x); h[5] = __float2half(v1.y);
        h[6] = __float2half(v1.z); h[7] = __float2half(v1.w);
        ((uint4*)g_A)[idx] = *(uint4*)h;
    } else {
        int bb = blockIdx.x - CONVA_BLOCKS;
        const int c0 = (bb % CONVB_BX) * 32;
        const int k0 = (bb / CONVB_BX) * 64;
        #pragma unroll
        for (int i = 0; i < 8; ++i) {
            int idx = threadIdx.x + i * 256;
            int kl = idx >> 5, cl = idx & 31;
            int colp = c0 + cl, u = colp >> 2, gate = colp & 3;
            int zcol = gate * 512 + u;
            int k = k0 + kl;
            float v = (k < 512) ? W[(size_t)k * NTOT + zcol]
                                : R[(size_t)(k - 512) * NTOT + zcol];
            s[kl][cl] = __float2half(v);
        }
        __syncthreads();
        const int cl = threadIdx.x >> 3;
        const int ks = (threadIdx.x & 7) * 8;
        __half tmp[8];
        #pragma unroll
        for (int j = 0; j < 8; ++j) tmp[j] = s[ks + j][cl];
        *(uint4*)&g_B[(size_t)(c0 + cl) * KK + k0 + ks] = *(uint4*)tmp;
    }
}

// -------- fused GEMM + gates: warp tile 64x64 --------
__global__ __launch_bounds__(256, 1)
void lstm_mma(const float* __restrict__ Cprev,
              const float* __restrict__ bias,
              float* __restrict__ out)
{
    extern __shared__ __align__(128) char smem[];
    const uint32_t sm = s2u(smem);
    const int tid = threadIdx.x, wid = tid >> 5, lane = tid & 31;
    const int warp_m = wid & 1;             // 0..1 (64 rows)
    const int warp_n = wid >> 1;            // 0..3 (64 cols)
    const int m0 = blockIdx.y * BM;
    const int n0 = blockIdx.x * BN;

    float acc[4][8][4];
    #pragma unroll
    for (int mi = 0; mi < 4; ++mi)
        #pragma unroll
        for (int ni = 0; ni < 8; ++ni)
            #pragma unroll
            for (int r = 0; r < 4; ++r) acc[mi][ni][r] = 0.0f;

    const int lr = tid >> 2, ls = tid & 3;

    auto load_stage = [&](int t, int stg) {
        const uint32_t sb = sm + stg * STAGEB;
        const int kb = t * BK;
        // A: 128 rows
        cp16(sb + lr * ROWB + ls * 16,
             g_A + (size_t)(m0 + lr) * KK + kb + ls * 8);
        cp16(sb + (lr + 64) * ROWB + ls * 16,
             g_A + (size_t)(m0 + lr + 64) * KK + kb + ls * 8);
        // B: 256 rows
        #pragma unroll
        for (int j = 0; j < 4; ++j) {
            int r = lr + j * 64;
            cp16(sb + ATILE + r * ROWB + ls * 16,
                 g_B + (size_t)(n0 + r) * KK + kb + ls * 8);
        }
    };

    const uint32_t aoff = (warp_m * 64 + (lane & 15)) * ROWB + ((lane >> 4) << 4);
    const uint32_t boff = ATILE
        + (warp_n * 64 + (lane & 7) + ((lane & 16) >> 1)) * ROWB + ((lane & 8) << 1);

    uint32_t aC[4][4], bC[4][4], aN[4][4], bN[4][4];

    #define LD_FRAGS(A_, B_, sb_, ks_) do {                                  \
        _Pragma("unroll")                                                    \
        for (int mi = 0; mi < 4; ++mi)                                       \
            ldsm4((A_)[mi], (sb_) + aoff + mi * (16 * ROWB) + (ks_) * 32);   \
        _Pragma("unroll")                                                    \
        for (int nj = 0; nj < 4; ++nj)                                       \
            ldsm4((B_)[nj], (sb_) + boff + nj * (16 * ROWB) + (ks_) * 32);   \
    } while (0)

    #define MMA_ALL(A_, B_) do {                                             \
        _Pragma("unroll")                                                    \
        for (int mi = 0; mi < 4; ++mi)                                       \
            _Pragma("unroll")                                                \
            for (int ni = 0; ni < 8; ++ni)                                   \
                mma16816(acc[mi][ni], (A_)[mi], &(B_)[ni >> 1][(ni & 1) * 2]);\
    } while (0)

    load_stage(0, 0); CP_COMMIT();
    load_stage(1, 1); CP_COMMIT();
    load_stage(2, 2); CP_COMMIT();
    CP_WAIT2();
    __syncthreads();
    LD_FRAGS(aC, bC, sm, 0);            // stage 0, ks 0

    for (int t = 0; t < KT; ++t) {
        const uint32_t sb = sm + (t & 3) * STAGEB;
        LD_FRAGS(aN, bN, sb, 1);        // ks 1 (latency hidden under MMA ks0)
        MMA_ALL(aC, bC);

        if (t + 3 < KT) load_stage(t + 3, (t + 3) & 3);
        CP_COMMIT();

        if (t + 1 < KT) {
            CP_WAIT2();
            __syncthreads();
            LD_FRAGS(aC, bC, sm + ((t + 1) & 3) * STAGEB, 0);  // next iter ks0
        }
        MMA_ALL(aN, bN);
    }

    // ---- epilogue: stage z[128][256] through smem ----
    __syncthreads();
    float* zs = (float*)smem;               // [128][260]
    const int g = lane >> 2, c2 = (lane & 3) * 2;
    #pragma unroll
    for (int mi = 0; mi < 4; ++mi) {
        const int r0 = warp_m * 64 + mi * 16 + g;
        #pragma unroll
        for (int ni = 0; ni < 8; ++ni) {
            const int col = warp_n * 64 + ni * 8 + c2;
            zs[r0 * 260 + col]           = acc[mi][ni][0];
            zs[r0 * 260 + col + 1]       = acc[mi][ni][1];
            zs[(r0 + 8) * 260 + col]     = acc[mi][ni][2];
            zs[(r0 + 8) * 260 + col + 1] = acc[mi][ni][3];
        }
    }
    __syncthreads();

    const size_t BU = (size_t)MB * UU;
    #pragma unroll
    for (int i = 0; i < 8; ++i) {
        int q   = tid + i * 256;            // 0..2047 (groups of 4 u)
        int row = q >> 4;                   // 0..127
        int ul0 = (q & 15) * 4;             // 0..60
        float4 z0 = *(float4*)&zs[row * 260 + ul0 * 4];
        float4 z1 = *(float4*)&zs[row * 260 + ul0 * 4 + 4];
        float4 z2 = *(float4*)&zs[row * 260 + ul0 * 4 + 8];
        float4 z3 = *(float4*)&zs[row * 260 + ul0 * 4 + 12];
        int u0 = blockIdx.x * 64 + ul0;
        float4 bi = *(const float4*)(bias + u0);
        float4 bf = *(const float4*)(bias + 512 + u0);
        float4 bg = *(const float4*)(bias + 1024 + u0);
        float4 bo = *(const float4*)(bias + 1536 + u0);
        float4 cv = *(const float4*)(Cprev + (size_t)(m0 + row) * UU + u0);

        const float* zq[4] = {(float*)&z0, (float*)&z1, (float*)&z2, (float*)&z3};
        const float* pbi = (const float*)&bi; const float* pbf = (const float*)&bf;
        const float* pbg = (const float*)&bg; const float* pbo = (const float*)&bo;
        const float* pc  = (const float*)&cv;

        float4 hv4, cv4;
        float* ph = (float*)&hv4; float* pcn = (float*)&cv4;
        #pragma unroll
        for (int l = 0; l < 4; ++l) {
            float zi = zq[l][0] + pbi[l];
            float zf = zq[l][1] + pbf[l];
            float zg = zq[l][2] + pbg[l];
            float zo = zq[l][3] + pbo[l];
            float cn = sigf(zf) * pc[l] + sigf(zi) * tanhf_fast(zg);
            pcn[l] = cn;
            ph[l]  = sigf(zo) * tanhf_fast(cn);
        }
        size_t o = (size_t)(m0 + row) * UU + u0;
        *(float4*)(out + o)          = hv4;
        *(float4*)(out + o + BU)     = hv4;
        *(float4*)(out + o + 2 * BU) = cv4;
    }
}

// -------- launch --------
extern "C" void kernel_launch(void* const* d_in, const int* in_sizes, int n_in,
                              void* d_out, int out_size)
{
    const float* X    = (const float*)d_in[0];
    const float* H    = (const float*)d_in[1];
    const float* C    = (const float*)d_in[2];
    const float* W    = (const float*)d_in[3];
    const float* R    = (const float*)d_in[4];
    const float* bias = (const float*)d_in[5];
    float* out = (float*)d_out;

    static bool attr_done = false;
    if (!attr_done) {
        cudaFuncSetAttribute(lstm_mma,
                             cudaFuncAttributeMaxDynamicSharedMemorySize, SMEM_DYN);
        attr_done = true;
    }

    conv_all<<<CONVA_BLOCKS + CONVB_BLOCKS, 256>>>(X, H, W, R);

    dim3 grid(NTOT / BN, MB / BM);          // (8, 64)
    lstm_mma<<<grid, 256, SMEM_DYN>>>(C, bias, out);
}